// round 15
// baseline (speedup 1.0000x reference)
#include <cuda_runtime.h>
#include <cuda_fp16.h>
#include <cstdint>

#define NN 4096
#define FF 256

// ---------------- scratch (device globals; no allocations) ----------------
__device__ float g_h[NN * FF];                    // 4 MB fp32 h
__device__ float g_e1[NN];
__device__ float g_e2[NN];
__device__ float g_tw[NN];                        // e1[r] * t[r]
__device__ float g_wnode[NN];
__device__ unsigned int g_hmax_bits;              // max |h| (float bits, >=0)
__device__ float g_S;                             // fp16 scale
__device__ float g_invS;
__device__ uint32_t g_adjbits[(size_t)NN * 128];  // 2 MB adj bitmask [4096][128 words]
__device__ __half g_gh[(size_t)NN * FF];          // 2 MB  S * wnode_j * h[j][n], fp16
__device__ __half g_xh[(size_t)NN * FF];          // 2 MB  x as fp16
__device__ __half g_wh[(size_t)FF * FF];          // 128KB W as fp16
__device__ float g_part[4 * (size_t)NN * FF];     // 16 MB split-K partials

// ---------------- mma / ldmatrix / cp.async helpers ----------------
__device__ __forceinline__ void mma_f16(float& c0, float& c1, float& c2, float& c3,
                                        uint32_t a0, uint32_t a1, uint32_t a2, uint32_t a3,
                                        uint32_t b0, uint32_t b1) {
    asm volatile(
        "mma.sync.aligned.m16n8k16.row.col.f32.f16.f16.f32 "
        "{%0,%1,%2,%3}, {%4,%5,%6,%7}, {%8,%9}, {%0,%1,%2,%3};\n"
        : "+f"(c0), "+f"(c1), "+f"(c2), "+f"(c3)
        : "r"(a0), "r"(a1), "r"(a2), "r"(a3), "r"(b0), "r"(b1));
}
__device__ __forceinline__ void ldsm4(uint32_t& r0, uint32_t& r1, uint32_t& r2, uint32_t& r3,
                                      uint32_t addr) {
    asm volatile("ldmatrix.sync.aligned.m8n8.x4.shared.b16 {%0,%1,%2,%3}, [%4];"
                 : "=r"(r0), "=r"(r1), "=r"(r2), "=r"(r3)
                 : "r"(addr));
}
__device__ __forceinline__ void ldsm4t(uint32_t& r0, uint32_t& r1, uint32_t& r2, uint32_t& r3,
                                       uint32_t addr) {
    asm volatile("ldmatrix.sync.aligned.m8n8.x4.trans.shared.b16 {%0,%1,%2,%3}, [%4];"
                 : "=r"(r0), "=r"(r1), "=r"(r2), "=r"(r3)
                 : "r"(addr));
}
__device__ __forceinline__ void cp16(uint32_t dst, const void* src) {
    asm volatile("cp.async.cg.shared.global [%0], [%1], 16;" :: "r"(dst), "l"(src));
}
#define CP_COMMIT() asm volatile("cp.async.commit_group;" ::: "memory")
#define CP_WAIT0() asm volatile("cp.async.wait_group 0;" ::: "memory")
#define CP_WAIT2() asm volatile("cp.async.wait_group 2;" ::: "memory")
#define CP_WAIT3() asm volatile("cp.async.wait_group 3;" ::: "memory")

// ---------------- kernel P: pack adj -> bitmask (no e2 dependency; overlap stream) ----------------
__global__ __launch_bounds__(256) void pack_kernel(const int* __restrict__ adj) {
    const int t = threadIdx.x;
    const int r0 = blockIdx.x * 8;
#pragma unroll
    for (int rr = 0; rr < 8; ++rr) {
        const int r = r0 + rr;
        const int4* arow = (const int4*)(adj + (size_t)r * 4096) + t * 4;
        uint32_t mask = 0;
#pragma unroll
        for (int q = 0; q < 4; q++) {
            int4 a = arow[q];
            mask |= ((uint32_t)(a.x == 1) << (q * 4)) | ((uint32_t)(a.y == 1) << (q * 4 + 1)) |
                    ((uint32_t)(a.z == 1) << (q * 4 + 2)) | ((uint32_t)(a.w == 1) << (q * 4 + 3));
        }
        // thread t owns cols [t*16, t*16+16) -> halfword t of the row's bit array
        ((uint16_t*)(g_adjbits + (size_t)r * 128))[t] = (uint16_t)mask;
    }
}

// ---------------- kernel 0: convert x, W to fp16 ----------------
__global__ __launch_bounds__(256) void convert_kernel(const float* __restrict__ x,
                                                      const float* __restrict__ W) {
    const int i = blockIdx.x * 256 + threadIdx.x;  // float4 index
    if (i < 262144) {                              // x: 1048576 floats
        float4 v = ((const float4*)x)[i];
        __half2 h0 = {__float2half(v.x), __float2half(v.y)};
        __half2 h1 = {__float2half(v.z), __float2half(v.w)};
        ((__half2*)g_xh)[i * 2] = h0;
        ((__half2*)g_xh)[i * 2 + 1] = h1;
    } else {
        int j = i - 262144;
        if (j < 16384) {                           // W: 65536 floats
            float4 v = ((const float4*)W)[j];
            __half2 h0 = {__float2half(v.x), __float2half(v.y)};
            __half2 h1 = {__float2half(v.z), __float2half(v.w)};
            ((__half2*)g_wh)[j * 2] = h0;
            ((__half2*)g_wh)[j * 2 + 1] = h1;
        }
    }
}

// ---------------- kernel 1: h = x @ W^T + b (HMMA fp16, single stage) ----------------
#define H_STRIDE 264   // halves per smem row (256 + 8 pad)
#define H_SMEM ((64 + 128) * H_STRIDE * 2)   // 101376 bytes

__global__ __launch_bounds__(256) void gemm_h_hmma_kernel(const float* __restrict__ b) {
    extern __shared__ __align__(16) __half hsm[];
    __half* xs = hsm;                 // 64 x H_STRIDE
    __half* ws = hsm + 64 * H_STRIDE; // 128 x H_STRIDE
    const int t = threadIdx.x;
    const int warp = t >> 5, lane = t & 31;
    const int wm = warp & 1, wn = warp >> 1;
    const int m0 = blockIdx.x * 64;
    const int n0 = blockIdx.y * 128;

    {
        uint32_t xb = (uint32_t)__cvta_generic_to_shared(xs);
        uint32_t wb = (uint32_t)__cvta_generic_to_shared(ws);
#pragma unroll
        for (int i = 0; i < 8; i++) {   // x: 64 rows x 32 chunks
            int q = t + i * 256;
            int row = q >> 5, seg = q & 31;
            cp16(xb + (row * H_STRIDE + seg * 8) * 2,
                 g_xh + (size_t)(m0 + row) * 256 + seg * 8);
        }
#pragma unroll
        for (int i = 0; i < 16; i++) {  // W: 128 rows x 32 chunks
            int q = t + i * 256;
            int row = q >> 5, seg = q & 31;
            cp16(wb + (row * H_STRIDE + seg * 8) * 2,
                 g_wh + (size_t)(n0 + row) * 256 + seg * 8);
        }
        CP_COMMIT();
    }
    CP_WAIT0();
    __syncthreads();

    float c[2][4][4];
#pragma unroll
    for (int i = 0; i < 2; i++)
#pragma unroll
        for (int j = 0; j < 4; j++)
#pragma unroll
            for (int q = 0; q < 4; q++) c[i][j][q] = 0.f;

#pragma unroll
    for (int kt = 0; kt < 16; ++kt) {
        const int kcol = kt * 16 + ((lane >> 4) << 3);
        uint32_t a[2][4];
#pragma unroll
        for (int mi = 0; mi < 2; ++mi) {
            int row = wm * 32 + mi * 16 + (lane & 15);
            uint32_t addr = (uint32_t)__cvta_generic_to_shared(xs + row * H_STRIDE + kcol);
            ldsm4(a[mi][0], a[mi][1], a[mi][2], a[mi][3], addr);
        }
#pragma unroll
        for (int ng = 0; ng < 2; ++ng) {
            int nrow = wn * 32 + ng * 16 + (lane & 15);
            uint32_t r0, r1, r2, r3;
            uint32_t addr = (uint32_t)__cvta_generic_to_shared(ws + nrow * H_STRIDE + kcol);
            ldsm4(r0, r1, r2, r3, addr);
#pragma unroll
            for (int mi = 0; mi < 2; ++mi) {
                mma_f16(c[mi][ng * 2][0], c[mi][ng * 2][1],
                        c[mi][ng * 2][2], c[mi][ng * 2][3],
                        a[mi][0], a[mi][1], a[mi][2], a[mi][3], r0, r2);
                mma_f16(c[mi][ng * 2 + 1][0], c[mi][ng * 2 + 1][1],
                        c[mi][ng * 2 + 1][2], c[mi][ng * 2 + 1][3],
                        a[mi][0], a[mi][1], a[mi][2], a[mi][3], r1, r3);
            }
        }
    }

    const int g = lane >> 2, tg = lane & 3;
#pragma unroll
    for (int mi = 0; mi < 2; ++mi) {
        int row0 = m0 + wm * 32 + mi * 16 + g;
#pragma unroll
        for (int nf = 0; nf < 4; ++nf) {
            int col = n0 + wn * 32 + nf * 8 + tg * 2;
            float b0 = b[col], b1 = b[col + 1];
            float2 v0 = {c[mi][nf][0] + b0, c[mi][nf][1] + b1};
            float2 v1 = {c[mi][nf][2] + b0, c[mi][nf][3] + b1};
            *(float2*)(g_h + (size_t)row0 * 256 + col) = v0;
            *(float2*)(g_h + (size_t)(row0 + 8) * 256 + col) = v1;
        }
    }
}

// ---------------- kernel 2: e1/e2 = exp(h.w1/2); also global max|h| ----------------
__global__ __launch_bounds__(256) void a12_kernel(const float* __restrict__ att_w) {
    __shared__ float aw[512];
    const int t = threadIdx.x;
    aw[t] = att_w[t];
    aw[t + 256] = att_w[t + 256];
    __syncthreads();
    const int warp = t >> 5, lane = t & 31;
    const int row = blockIdx.x * 8 + warp;
    const float* hr = g_h + (size_t)row * 256;
    float s1 = 0.f, s2 = 0.f, hm = 0.f;
#pragma unroll
    for (int q = 0; q < 2; q++) {
        int f = lane * 8 + q * 4;
        float4 hv = *(const float4*)(hr + f);
        float4 w1 = *(const float4*)(aw + f);
        float4 w2 = *(const float4*)(aw + 256 + f);
        s1 += hv.x * w1.x + hv.y * w1.y + hv.z * w1.z + hv.w * w1.w;
        s2 += hv.x * w2.x + hv.y * w2.y + hv.z * w2.z + hv.w * w2.w;
        hm = fmaxf(hm, fmaxf(fmaxf(fabsf(hv.x), fabsf(hv.y)),
                             fmaxf(fabsf(hv.z), fabsf(hv.w))));
    }
#pragma unroll
    for (int d = 16; d; d >>= 1) {
        s1 += __shfl_down_sync(0xffffffffu, s1, d);
        s2 += __shfl_down_sync(0xffffffffu, s2, d);
        hm = fmaxf(hm, __shfl_down_sync(0xffffffffu, hm, d));
    }
    if (lane == 0) {
        g_e1[row] = expf(s1);
        g_e2[row] = expf(s2);
        atomicMax(&g_hmax_bits, __float_as_uint(hm));  // |h|>=0: uint order == float order
    }
}

// ---------------- kernel 3: t[i] from bitmask + smem e2; tw = e1*t ----------------
// 8 warps/block, one row per warp; lane covers cols [lane*128, lane*128+128)
__global__ __launch_bounds__(256) void tstat_kernel() {
    __shared__ float se2[4096];
    const int t = threadIdx.x, lane = t & 31, warp = t >> 5;
#pragma unroll
    for (int i = 0; i < 4; i++)
        ((float4*)se2)[t + i * 256] = ((const float4*)g_e2)[t + i * 256];
    __syncthreads();

    const int r = blockIdx.x * 8 + warp;
    uint4 w4 = *(const uint4*)(g_adjbits + (size_t)r * 128 + lane * 4);
    uint32_t wd[4] = {w4.x, w4.y, w4.z, w4.w};
    float s = 0.f;
#pragma unroll
    for (int q = 0; q < 4; q++) {
        const float* base = se2 + lane * 128 + q * 32;
        uint32_t w = wd[q];
#pragma unroll
        for (int b2 = 0; b2 < 32; b2++) {
            s += ((w >> b2) & 1u) ? base[b2] : 0.f;
        }
    }
#pragma unroll
    for (int d = 16; d; d >>= 1) s += __shfl_down_sync(0xffffffffu, s, d);
    if (lane == 0) g_tw[r] = g_e1[r] * s;
}

// ---------------- kernel 4: denom + w_node ordered scan + scale S ----------------
__global__ __launch_bounds__(1024) void wnode_kernel(const int* __restrict__ adj) {
    __shared__ int warp_sums[32];
    __shared__ float redf[32];
    __shared__ int s_base;
    __shared__ float s_inv;
    const int t = threadIdx.x, lane = t & 31, warp = t >> 5;

    // denom = sum_r g_tw[r]
    float sd = 0.f;
#pragma unroll
    for (int i = 0; i < 4; i++) sd += g_tw[t + i * 1024];
#pragma unroll
    for (int d = 16; d; d >>= 1) sd += __shfl_down_sync(0xffffffffu, sd, d);
    if (lane == 0) redf[warp] = sd;
    __syncthreads();
    if (warp == 0) {
        float v = redf[lane];
#pragma unroll
        for (int d = 16; d; d >>= 1) v += __shfl_down_sync(0xffffffffu, v, d);
        if (lane == 0) {
            s_inv = 1.f / v;
            s_base = 0;
        }
    }
    __syncthreads();
    const float inv = s_inv;

    for (int r = 0; r < NN; ++r) {
        int base = s_base;
        if (base >= NN) break;
        int4 a = *(const int4*)(adj + (size_t)r * 4096 + t * 4);
        int f0 = (a.x == 1), f1 = (a.y == 1), f2 = (a.z == 1), f3 = (a.w == 1);
        int cnt = f0 + f1 + f2 + f3;
        int incl = cnt;
#pragma unroll
        for (int d = 1; d < 32; d <<= 1) {
            int v = __shfl_up_sync(0xffffffffu, incl, d);
            if (lane >= d) incl += v;
        }
        if (lane == 31) warp_sums[warp] = incl;
        __syncthreads();
        if (warp == 0) {
            int v = warp_sums[lane];
#pragma unroll
            for (int d = 1; d < 32; d <<= 1) {
                int u = __shfl_up_sync(0xffffffffu, v, d);
                if (lane >= d) v += u;
            }
            warp_sums[lane] = v;
        }
        __syncthreads();
        int wbase = (warp == 0) ? 0 : warp_sums[warp - 1];
        int o = base + wbase + (incl - cnt);
        float er = g_e1[r];
        float4 ev = *(const float4*)(g_e2 + t * 4);
        if (f0) { if (o < NN) g_wnode[o] = er * ev.x * inv; o++; }
        if (f1) { if (o < NN) g_wnode[o] = er * ev.y * inv; o++; }
        if (f2) { if (o < NN) g_wnode[o] = er * ev.z * inv; o++; }
        if (f3) { if (o < NN) g_wnode[o] = er * ev.w * inv; o++; }
        __syncthreads();
        if (t == 0) s_base = base + warp_sums[31];
        __syncthreads();
    }

    // scale S = 4096 / (max w * max|h|)
    __syncthreads();
    float wm = 0.f;
    for (int i = t; i < NN; i += 1024) wm = fmaxf(wm, g_wnode[i]);
#pragma unroll
    for (int d = 16; d; d >>= 1) wm = fmaxf(wm, __shfl_down_sync(0xffffffffu, wm, d));
    if (lane == 0) redf[warp] = wm;
    __syncthreads();
    if (warp == 0) {
        float v = redf[lane];
#pragma unroll
        for (int d = 16; d; d >>= 1) v = fmaxf(v, __shfl_down_sync(0xffffffffu, v, d));
        if (lane == 0) {
            float hmax = __uint_as_float(g_hmax_bits);
            float denom2 = v * hmax;
            g_S = 4096.f / denom2;
            g_invS = denom2 * (1.f / 4096.f);
        }
    }
}

// ---------------- kernel 5: g = S * wnode .* h -> fp16 [4096][256] ----------------
__global__ __launch_bounds__(128) void gscale_kernel() {
    const int j = blockIdx.x, t = threadIdx.x;
    const float ws = g_wnode[j] * g_S;
    float2 hv = *(const float2*)(g_h + (size_t)j * 256 + t * 2);
    __half2 o;
    o.x = __float2half(ws * hv.x);
    o.y = __float2half(ws * hv.y);
    ((__half2*)g_gh)[j * 128 + t] = o;
}

// ---------------- kernel 6: HMMA GEMM (bits-A expansion + R3 pipeline) ----------------
#define BITS_STRIDE 36                          // words per bits row (16B-aligned)
#define BITS_BYTES (128 * BITS_STRIDE * 4)      // 18432
#define A_STRIDE 72                             // halves per A smem row
#define B_STRIDE 264                            // halves per B smem row
#define A_STAGE_HALVES (128 * A_STRIDE)         // 9216
#define B_STAGE_HALVES (64 * B_STRIDE)          // 16896
#define STAGE_HALVES (A_STAGE_HALVES + B_STAGE_HALVES)
#define SMEM_DYN (BITS_BYTES + 3 * STAGE_HALVES * 2 + 32)

__global__ __launch_bounds__(512, 1) void gemm_out_hmma_kernel() {
    extern __shared__ __align__(16) char smem_raw[];
    uint32_t* bitsS = (uint32_t*)smem_raw;
    __half* stages = (__half*)(smem_raw + BITS_BYTES);
    const int t = threadIdx.x;
    const int warp = t >> 5, lane = t & 31;
    const int wm = warp & 3, wn = warp >> 2;
    const int m0 = blockIdx.x * 128;
    const int kbase = blockIdx.y * 1024;
    const int kw0 = blockIdx.y * 32;

    __half* As[3];
    __half* Bs[3];
#pragma unroll
    for (int s = 0; s < 3; s++) {
        As[s] = stages + s * STAGE_HALVES;
        Bs[s] = As[s] + A_STAGE_HALVES;
    }

    float c[2][8][4];
#pragma unroll
    for (int i = 0; i < 2; i++)
#pragma unroll
        for (int j = 0; j < 8; j++)
#pragma unroll
            for (int q = 0; q < 4; q++) c[i][j][q] = 0.f;

    {
        uint32_t bb = (uint32_t)__cvta_generic_to_shared(bitsS);
#pragma unroll
        for (int i = 0; i < 2; i++) {
            int task = t + i * 512;
            int row = task >> 3, seg = task & 7;
            cp16(bb + (row * BITS_STRIDE + seg * 4) * 4,
                 g_adjbits + (size_t)(m0 + row) * 128 + kw0 + seg * 4);
        }
        CP_COMMIT();
    }

    auto load_B = [&](int slot, int kt) {
        const int k0 = kbase + kt * 64;
        uint32_t bbase = (uint32_t)__cvta_generic_to_shared(Bs[slot]);
#pragma unroll
        for (int i = 0; i < 4; i++) {
            int q = t + i * 512;
            int row = q >> 5, seg = q & 31;
            cp16(bbase + (row * B_STRIDE + seg * 8) * 2,
                 g_gh + (size_t)(k0 + row) * 256 + seg * 8);
        }
        CP_COMMIT();
    };

    const int xrow = t >> 2, xq = t & 3;
    auto expand_A = [&](int slot, int kt) {
        uint32_t w = bitsS[xrow * BITS_STRIDE + kt * 2 + (xq >> 1)];
        uint32_t b16 = (w >> ((xq & 1) * 16)) & 0xFFFFu;
        uint32_t u[8];
#pragma unroll
        for (int j = 0; j < 8; j++) {
            u[j] = ((b16 >> (2 * j)) & 1u) * 0x3C00u |
                   ((b16 >> (2 * j + 1)) & 1u) * 0x3C000000u;
        }
        __half* dst = As[slot] + xrow * A_STRIDE + xq * 16;
        *(uint4*)dst = make_uint4(u[0], u[1], u[2], u[3]);
        *(uint4*)(dst + 8) = make_uint4(u[4], u[5], u[6], u[7]);
    };

    load_B(0, 0);
    load_B(1, 1);
    load_B(2, 2);
    CP_WAIT3();
    __syncthreads();
    expand_A(0, 0);
    expand_A(1, 1);
    expand_A(2, 2);

    for (int kt = 0; kt < 16; ++kt) {
        const int slot = kt % 3;
        CP_WAIT2();
        __syncthreads();
        const __half* a_s = As[slot];
        const __half* b_s = Bs[slot];
#pragma unroll
        for (int ks = 0; ks < 4; ++ks) {
            uint32_t a[2][4];
#pragma unroll
            for (int mi = 0; mi < 2; ++mi) {
                int row = wm * 32 + mi * 16 + (lane & 15);
                int col = ks * 16 + ((lane >> 4) << 3);
                uint32_t addr =
                    (uint32_t)__cvta_generic_to_shared(a_s + row * A_STRIDE + col);
                ldsm4(a[mi][0], a[mi][1], a[mi][2], a[mi][3], addr);
            }
#pragma unroll
            for (int ng = 0; ng < 4; ++ng) {
                int krow = ks * 16 + (lane & 15);
                int col = wn * 64 + ng * 16 + ((lane >> 4) << 3);
                uint32_t b0, b1, b2, b3;
                uint32_t addr =
                    (uint32_t)__cvta_generic_to_shared(b_s + krow * B_STRIDE + col);
                ldsm4t(b0, b1, b2, b3, addr);
#pragma unroll
                for (int mi = 0; mi < 2; ++mi) {
                    mma_f16(c[mi][ng * 2][0], c[mi][ng * 2][1],
                            c[mi][ng * 2][2], c[mi][ng * 2][3],
                            a[mi][0], a[mi][1], a[mi][2], a[mi][3], b0, b1);
                    mma_f16(c[mi][ng * 2 + 1][0], c[mi][ng * 2 + 1][1],
                            c[mi][ng * 2 + 1][2], c[mi][ng * 2 + 1][3],
                            a[mi][0], a[mi][1], a[mi][2], a[mi][3], b2, b3);
                }
            }
        }
        __syncthreads();
        if (kt + 3 < 16) {
            expand_A(slot, kt + 3);
            load_B(slot, kt + 3);
        }
        CP_COMMIT();  // R3 pattern: unconditional extra group each iteration
    }

    // epilogue: fp32 partials
    float* dst = g_part + (size_t)blockIdx.y * NN * FF;
    const int g = lane >> 2, tg = lane & 3;
#pragma unroll
    for (int mi = 0; mi < 2; ++mi) {
        int row0 = m0 + wm * 32 + mi * 16 + g;
#pragma unroll
        for (int nb = 0; nb < 8; ++nb) {
            int col = wn * 64 + nb * 8 + tg * 2;
            float2 v0 = {c[mi][nb][0], c[mi][nb][1]};
            float2 v1 = {c[mi][nb][2], c[mi][nb][3]};
            *(float2*)(dst + (size_t)row0 * 256 + col) = v0;
            *(float2*)(dst + (size_t)(row0 + 8) * 256 + col) = v1;
        }
    }
}

// ---------------- kernel 7: out = relu(sum partials) * invS ----------------
__global__ __launch_bounds__(256) void relu_sum_kernel(float* __restrict__ out) {
    const float invS = g_invS;
    const size_t idx = (size_t)(blockIdx.x * 256 + threadIdx.x) * 4;
    float4 a = *(const float4*)(g_part + idx);
    float4 b = *(const float4*)(g_part + (size_t)NN * FF + idx);
    float4 c = *(const float4*)(g_part + 2 * (size_t)NN * FF + idx);
    float4 d = *(const float4*)(g_part + 3 * (size_t)NN * FF + idx);
    float4 v;
    v.x = fmaxf(a.x + b.x + c.x + d.x, 0.f) * invS;
    v.y = fmaxf(a.y + b.y + c.y + d.y, 0.f) * invS;
    v.z = fmaxf(a.z + b.z + c.z + d.z, 0.f) * invS;
    v.w = fmaxf(a.w + b.w + c.w + d.w, 0.f) * invS;
    *(float4*)(out + idx) = v;
}

// ---------------- launch ----------------
extern "C" void kernel_launch(void* const* d_in, const int* in_sizes, int n_in,
                              void* d_out, int out_size) {
    const float* x = (const float*)d_in[0];
    const int* adj = (const int*)d_in[1];
    const float* W = (const float*)d_in[2];
    const float* b = (const float*)d_in[3];
    const float* att_w = (const float*)d_in[4];
    // att_b cancels in the softmax ratio; unused.
    float* out = (float*)d_out;

    static bool init_done = false;
    static cudaStream_t s2;
    static cudaEvent_t ev_fork, ev_join;
    if (!init_done) {
        cudaFuncSetAttribute(gemm_out_hmma_kernel,
                             cudaFuncAttributeMaxDynamicSharedMemorySize, SMEM_DYN);
        cudaFuncSetAttribute(gemm_h_hmma_kernel,
                             cudaFuncAttributeMaxDynamicSharedMemorySize, H_SMEM);
        cudaStreamCreateWithFlags(&s2, cudaStreamNonBlocking);
        cudaEventCreateWithFlags(&ev_fork, cudaEventDisableTiming);
        cudaEventCreateWithFlags(&ev_join, cudaEventDisableTiming);
        init_done = true;
    }

    // fork: pack adj->bits on s2, overlapped with convert/gemm_h/a12
    cudaEventRecord(ev_fork, 0);
    cudaStreamWaitEvent(s2, ev_fork, 0);
    pack_kernel<<<512, 256, 0, s2>>>(adj);
    cudaEventRecord(ev_join, s2);

    convert_kernel<<<1088, 256>>>(x, W);
    gemm_h_hmma_kernel<<<dim3(64, 2), 256, H_SMEM>>>(b);
    a12_kernel<<<512, 256>>>(att_w);

    // join: tstat needs both bits (s2) and e2 (main stream)
    cudaStreamWaitEvent(0, ev_join, 0);
    tstat_kernel<<<512, 256>>>();
    wnode_kernel<<<1, 1024>>>(adj);
    gscale_kernel<<<4096, 128>>>();
    gemm_out_hmma_kernel<<<dim3(32, 4), 512, SMEM_DYN>>>();
    relu_sum_kernel<<<1024, 256>>>(out);
}

// round 16
// speedup vs baseline: 1.5110x; 1.5110x over previous
#include <cuda_runtime.h>
#include <cuda_fp16.h>
#include <cstdint>

#define NN 4096
#define FF 256

// ---------------- scratch (device globals; no allocations) ----------------
__device__ float g_h[NN * FF];                    // 4 MB fp32 h
__device__ float g_e1[NN];
__device__ float g_e2[NN];
__device__ float g_tw[NN];                        // e1[r] * t[r]
__device__ float g_wnode[NN];
__device__ unsigned int g_hmax_bits;              // max |h| (float bits, >=0)
__device__ float g_S;                             // fp16 scale
__device__ float g_invS;
__device__ uint32_t g_adjbits[(size_t)NN * 128];  // 2 MB adj bitmask [4096][128 words]
__device__ __half g_gh[(size_t)NN * FF];          // 2 MB  S * wnode_j * h[j][n], fp16
__device__ __half g_xh[(size_t)NN * FF];          // 2 MB  x as fp16
__device__ __half g_wh[(size_t)FF * FF];          // 128KB W as fp16
__device__ float g_part[4 * (size_t)NN * FF];     // 16 MB split-K partials

// ---------------- mma / ldmatrix / cp.async helpers ----------------
__device__ __forceinline__ void mma_f16(float& c0, float& c1, float& c2, float& c3,
                                        uint32_t a0, uint32_t a1, uint32_t a2, uint32_t a3,
                                        uint32_t b0, uint32_t b1) {
    asm volatile(
        "mma.sync.aligned.m16n8k16.row.col.f32.f16.f16.f32 "
        "{%0,%1,%2,%3}, {%4,%5,%6,%7}, {%8,%9}, {%0,%1,%2,%3};\n"
        : "+f"(c0), "+f"(c1), "+f"(c2), "+f"(c3)
        : "r"(a0), "r"(a1), "r"(a2), "r"(a3), "r"(b0), "r"(b1));
}
__device__ __forceinline__ void ldsm4(uint32_t& r0, uint32_t& r1, uint32_t& r2, uint32_t& r3,
                                      uint32_t addr) {
    asm volatile("ldmatrix.sync.aligned.m8n8.x4.shared.b16 {%0,%1,%2,%3}, [%4];"
                 : "=r"(r0), "=r"(r1), "=r"(r2), "=r"(r3)
                 : "r"(addr));
}
__device__ __forceinline__ void ldsm4t(uint32_t& r0, uint32_t& r1, uint32_t& r2, uint32_t& r3,
                                       uint32_t addr) {
    asm volatile("ldmatrix.sync.aligned.m8n8.x4.trans.shared.b16 {%0,%1,%2,%3}, [%4];"
                 : "=r"(r0), "=r"(r1), "=r"(r2), "=r"(r3)
                 : "r"(addr));
}
__device__ __forceinline__ void cp16(uint32_t dst, const void* src) {
    asm volatile("cp.async.cg.shared.global [%0], [%1], 16;" :: "r"(dst), "l"(src));
}
#define CP_COMMIT() asm volatile("cp.async.commit_group;" ::: "memory")
#define CP_WAIT0() asm volatile("cp.async.wait_group 0;" ::: "memory")
#define CP_WAIT2() asm volatile("cp.async.wait_group 2;" ::: "memory")
#define CP_WAIT3() asm volatile("cp.async.wait_group 3;" ::: "memory")

// ---------------- kernel 0: convert x, W to fp16 ----------------
__global__ __launch_bounds__(256) void convert_kernel(const float* __restrict__ x,
                                                      const float* __restrict__ W) {
    const int i = blockIdx.x * 256 + threadIdx.x;  // float4 index
    if (i < 262144) {                              // x: 1048576 floats
        float4 v = ((const float4*)x)[i];
        __half2 h0 = {__float2half(v.x), __float2half(v.y)};
        __half2 h1 = {__float2half(v.z), __float2half(v.w)};
        ((__half2*)g_xh)[i * 2] = h0;
        ((__half2*)g_xh)[i * 2 + 1] = h1;
    } else {
        int j = i - 262144;
        if (j < 16384) {                           // W: 65536 floats
            float4 v = ((const float4*)W)[j];
            __half2 h0 = {__float2half(v.x), __float2half(v.y)};
            __half2 h1 = {__float2half(v.z), __float2half(v.w)};
            ((__half2*)g_wh)[j * 2] = h0;
            ((__half2*)g_wh)[j * 2 + 1] = h1;
        }
    }
}

// ---------------- kernel 1: h = x @ W^T + b (HMMA fp16, single stage) ----------------
#define H_STRIDE 264   // halves per smem row (256 + 8 pad)
#define H_SMEM ((64 + 128) * H_STRIDE * 2)   // 101376 bytes

__global__ __launch_bounds__(256) void gemm_h_hmma_kernel(const float* __restrict__ b) {
    extern __shared__ __align__(16) __half hsm[];
    __half* xs = hsm;                 // 64 x H_STRIDE
    __half* ws = hsm + 64 * H_STRIDE; // 128 x H_STRIDE
    const int t = threadIdx.x;
    const int warp = t >> 5, lane = t & 31;
    const int wm = warp & 1, wn = warp >> 1;
    const int m0 = blockIdx.x * 64;
    const int n0 = blockIdx.y * 128;

    {
        uint32_t xb = (uint32_t)__cvta_generic_to_shared(xs);
        uint32_t wb = (uint32_t)__cvta_generic_to_shared(ws);
#pragma unroll
        for (int i = 0; i < 8; i++) {   // x: 64 rows x 32 chunks
            int q = t + i * 256;
            int row = q >> 5, seg = q & 31;
            cp16(xb + (row * H_STRIDE + seg * 8) * 2,
                 g_xh + (size_t)(m0 + row) * 256 + seg * 8);
        }
#pragma unroll
        for (int i = 0; i < 16; i++) {  // W: 128 rows x 32 chunks
            int q = t + i * 256;
            int row = q >> 5, seg = q & 31;
            cp16(wb + (row * H_STRIDE + seg * 8) * 2,
                 g_wh + (size_t)(n0 + row) * 256 + seg * 8);
        }
        CP_COMMIT();
    }
    CP_WAIT0();
    __syncthreads();

    float c[2][4][4];
#pragma unroll
    for (int i = 0; i < 2; i++)
#pragma unroll
        for (int j = 0; j < 4; j++)
#pragma unroll
            for (int q = 0; q < 4; q++) c[i][j][q] = 0.f;

#pragma unroll
    for (int kt = 0; kt < 16; ++kt) {
        const int kcol = kt * 16 + ((lane >> 4) << 3);
        uint32_t a[2][4];
#pragma unroll
        for (int mi = 0; mi < 2; ++mi) {
            int row = wm * 32 + mi * 16 + (lane & 15);
            uint32_t addr = (uint32_t)__cvta_generic_to_shared(xs + row * H_STRIDE + kcol);
            ldsm4(a[mi][0], a[mi][1], a[mi][2], a[mi][3], addr);
        }
#pragma unroll
        for (int ng = 0; ng < 2; ++ng) {
            int nrow = wn * 32 + ng * 16 + (lane & 15);
            uint32_t r0, r1, r2, r3;
            uint32_t addr = (uint32_t)__cvta_generic_to_shared(ws + nrow * H_STRIDE + kcol);
            ldsm4(r0, r1, r2, r3, addr);
#pragma unroll
            for (int mi = 0; mi < 2; ++mi) {
                mma_f16(c[mi][ng * 2][0], c[mi][ng * 2][1],
                        c[mi][ng * 2][2], c[mi][ng * 2][3],
                        a[mi][0], a[mi][1], a[mi][2], a[mi][3], r0, r2);
                mma_f16(c[mi][ng * 2 + 1][0], c[mi][ng * 2 + 1][1],
                        c[mi][ng * 2 + 1][2], c[mi][ng * 2 + 1][3],
                        a[mi][0], a[mi][1], a[mi][2], a[mi][3], r1, r3);
            }
        }
    }

    const int g = lane >> 2, tg = lane & 3;
#pragma unroll
    for (int mi = 0; mi < 2; ++mi) {
        int row0 = m0 + wm * 32 + mi * 16 + g;
#pragma unroll
        for (int nf = 0; nf < 4; ++nf) {
            int col = n0 + wn * 32 + nf * 8 + tg * 2;
            float b0 = b[col], b1 = b[col + 1];
            float2 v0 = {c[mi][nf][0] + b0, c[mi][nf][1] + b1};
            float2 v1 = {c[mi][nf][2] + b0, c[mi][nf][3] + b1};
            *(float2*)(g_h + (size_t)row0 * 256 + col) = v0;
            *(float2*)(g_h + (size_t)(row0 + 8) * 256 + col) = v1;
        }
    }
}

// ---------------- kernel 2: e1/e2 = exp(h.w1/2); 2 rows per warp for MLP ----------------
__global__ __launch_bounds__(256) void a12_kernel(const float* __restrict__ att_w) {
    __shared__ float aw[512];
    const int t = threadIdx.x;
    aw[t] = att_w[t];
    aw[t + 256] = att_w[t + 256];
    __syncthreads();
    const int warp = t >> 5, lane = t & 31;
    const int row = blockIdx.x * 16 + warp * 2;
    float s1[2] = {0.f, 0.f}, s2[2] = {0.f, 0.f};
    float hm = 0.f;
#pragma unroll
    for (int rr = 0; rr < 2; ++rr) {
        const float* hr = g_h + (size_t)(row + rr) * 256;
#pragma unroll
        for (int q = 0; q < 2; q++) {
            int f = lane * 8 + q * 4;
            float4 hv = *(const float4*)(hr + f);
            float4 w1 = *(const float4*)(aw + f);
            float4 w2 = *(const float4*)(aw + 256 + f);
            s1[rr] += hv.x * w1.x + hv.y * w1.y + hv.z * w1.z + hv.w * w1.w;
            s2[rr] += hv.x * w2.x + hv.y * w2.y + hv.z * w2.z + hv.w * w2.w;
            hm = fmaxf(hm, fmaxf(fmaxf(fabsf(hv.x), fabsf(hv.y)),
                                 fmaxf(fabsf(hv.z), fabsf(hv.w))));
        }
    }
#pragma unroll
    for (int d = 16; d; d >>= 1) {
        s1[0] += __shfl_down_sync(0xffffffffu, s1[0], d);
        s2[0] += __shfl_down_sync(0xffffffffu, s2[0], d);
        s1[1] += __shfl_down_sync(0xffffffffu, s1[1], d);
        s2[1] += __shfl_down_sync(0xffffffffu, s2[1], d);
        hm = fmaxf(hm, __shfl_down_sync(0xffffffffu, hm, d));
    }
    if (lane == 0) {
        g_e1[row] = expf(s1[0]);
        g_e2[row] = expf(s2[0]);
        g_e1[row + 1] = expf(s1[1]);
        g_e2[row + 1] = expf(s2[1]);
        atomicMax(&g_hmax_bits, __float_as_uint(hm));  // |h|>=0: uint order == float order
    }
}

// ---------------- kernel 3: 8 rows/block; e2 in REGISTERS; adj -> bitmask; tw = e1*t ----------------
__global__ __launch_bounds__(256) void row_stats_kernel(const int* __restrict__ adj) {
    __shared__ float wsum[8][8];
    const int t = threadIdx.x;
    const int lane = t & 31, warp = t >> 5;
    const int r0 = blockIdx.x * 8;

    // e2 slice for this thread's columns: loaded once, reused for all 8 rows
    float4 ev[4];
#pragma unroll
    for (int q = 0; q < 4; q++) ev[q] = ((const float4*)g_e2)[t * 4 + q];

#pragma unroll
    for (int rr = 0; rr < 8; ++rr) {
        const int r = r0 + rr;
        const int4* arow = (const int4*)(adj + (size_t)r * 4096) + t * 4;
        float s = 0.f;
        uint32_t mask = 0;
#pragma unroll
        for (int q = 0; q < 4; q++) {
            int4 a = arow[q];
            int f0 = (a.x == 1), f1 = (a.y == 1), f2 = (a.z == 1), f3 = (a.w == 1);
            s += (f0 ? ev[q].x : 0.f) + (f1 ? ev[q].y : 0.f) +
                 (f2 ? ev[q].z : 0.f) + (f3 ? ev[q].w : 0.f);
            mask |= ((uint32_t)f0 << (q * 4)) | ((uint32_t)f1 << (q * 4 + 1)) |
                    ((uint32_t)f2 << (q * 4 + 2)) | ((uint32_t)f3 << (q * 4 + 3));
        }
        // thread t owns cols [t*16, t*16+16) -> halfword t of the row's bit array
        ((uint16_t*)(g_adjbits + (size_t)r * 128))[t] = (uint16_t)mask;
#pragma unroll
        for (int d = 16; d; d >>= 1) s += __shfl_down_sync(0xffffffffu, s, d);
        if (lane == 0) wsum[rr][warp] = s;
    }
    __syncthreads();
    if (t < 8) {
        float tot = 0.f;
#pragma unroll
        for (int w2 = 0; w2 < 8; w2++) tot += wsum[t][w2];
        g_tw[r0 + t] = g_e1[r0 + t] * tot;
    }
}

// ---------------- kernel 4: denom + w_node ordered scan + scale S ----------------
__global__ __launch_bounds__(1024) void wnode_kernel(const int* __restrict__ adj) {
    __shared__ int warp_sums[32];
    __shared__ float redf[32];
    __shared__ int s_base;
    __shared__ float s_inv;
    const int t = threadIdx.x, lane = t & 31, warp = t >> 5;

    // denom = sum_r g_tw[r]
    float sd = 0.f;
#pragma unroll
    for (int i = 0; i < 4; i++) sd += g_tw[t + i * 1024];
#pragma unroll
    for (int d = 16; d; d >>= 1) sd += __shfl_down_sync(0xffffffffu, sd, d);
    if (lane == 0) redf[warp] = sd;
    __syncthreads();
    if (warp == 0) {
        float v = redf[lane];
#pragma unroll
        for (int d = 16; d; d >>= 1) v += __shfl_down_sync(0xffffffffu, v, d);
        if (lane == 0) {
            s_inv = 1.f / v;
            s_base = 0;
        }
    }
    __syncthreads();
    const float inv = s_inv;

    for (int r = 0; r < NN; ++r) {
        int base = s_base;
        if (base >= NN) break;
        int4 a = *(const int4*)(adj + (size_t)r * 4096 + t * 4);
        int f0 = (a.x == 1), f1 = (a.y == 1), f2 = (a.z == 1), f3 = (a.w == 1);
        int cnt = f0 + f1 + f2 + f3;
        int incl = cnt;
#pragma unroll
        for (int d = 1; d < 32; d <<= 1) {
            int v = __shfl_up_sync(0xffffffffu, incl, d);
            if (lane >= d) incl += v;
        }
        if (lane == 31) warp_sums[warp] = incl;
        __syncthreads();
        if (warp == 0) {
            int v = warp_sums[lane];
#pragma unroll
            for (int d = 1; d < 32; d <<= 1) {
                int u = __shfl_up_sync(0xffffffffu, v, d);
                if (lane >= d) v += u;
            }
            warp_sums[lane] = v;
        }
        __syncthreads();
        int wbase = (warp == 0) ? 0 : warp_sums[warp - 1];
        int o = base + wbase + (incl - cnt);
        float er = g_e1[r];
        float4 ev = *(const float4*)(g_e2 + t * 4);
        if (f0) { if (o < NN) g_wnode[o] = er * ev.x * inv; o++; }
        if (f1) { if (o < NN) g_wnode[o] = er * ev.y * inv; o++; }
        if (f2) { if (o < NN) g_wnode[o] = er * ev.z * inv; o++; }
        if (f3) { if (o < NN) g_wnode[o] = er * ev.w * inv; o++; }
        __syncthreads();
        if (t == 0) s_base = base + warp_sums[31];
        __syncthreads();
    }

    // scale S = 4096 / (max w * max|h|)
    __syncthreads();
    float wm = 0.f;
    for (int i = t; i < NN; i += 1024) wm = fmaxf(wm, g_wnode[i]);
#pragma unroll
    for (int d = 16; d; d >>= 1) wm = fmaxf(wm, __shfl_down_sync(0xffffffffu, wm, d));
    if (lane == 0) redf[warp] = wm;
    __syncthreads();
    if (warp == 0) {
        float v = redf[lane];
#pragma unroll
        for (int d = 16; d; d >>= 1) v = fmaxf(v, __shfl_down_sync(0xffffffffu, v, d));
        if (lane == 0) {
            float hmax = __uint_as_float(g_hmax_bits);
            float denom2 = v * hmax;
            g_S = 4096.f / denom2;
            g_invS = denom2 * (1.f / 4096.f);
        }
    }
}

// ---------------- kernel 5: g = S * wnode .* h -> fp16 [4096][256] ----------------
__global__ __launch_bounds__(128) void gscale_kernel() {
    const int j = blockIdx.x, t = threadIdx.x;
    const float ws = g_wnode[j] * g_S;
    float2 hv = *(const float2*)(g_h + (size_t)j * 256 + t * 2);
    __half2 o;
    o.x = __float2half(ws * hv.x);
    o.y = __float2half(ws * hv.y);
    ((__half2*)g_gh)[j * 128 + t] = o;
}

// ---------------- kernel 6: HMMA GEMM (bits-A expansion + R3 pipeline) ----------------
#define BITS_STRIDE 36                          // words per bits row (16B-aligned)
#define BITS_BYTES (128 * BITS_STRIDE * 4)      // 18432
#define A_STRIDE 72                             // halves per A smem row
#define B_STRIDE 264                            // halves per B smem row
#define A_STAGE_HALVES (128 * A_STRIDE)         // 9216
#define B_STAGE_HALVES (64 * B_STRIDE)          // 16896
#define STAGE_HALVES (A_STAGE_HALVES + B_STAGE_HALVES)
#define SMEM_DYN (BITS_BYTES + 3 * STAGE_HALVES * 2 + 32)

__global__ __launch_bounds__(512, 1) void gemm_out_hmma_kernel() {
    extern __shared__ __align__(16) char smem_raw[];
    uint32_t* bitsS = (uint32_t*)smem_raw;
    __half* stages = (__half*)(smem_raw + BITS_BYTES);
    const int t = threadIdx.x;
    const int warp = t >> 5, lane = t & 31;
    const int wm = warp & 3, wn = warp >> 2;
    const int m0 = blockIdx.x * 128;
    const int kbase = blockIdx.y * 1024;
    const int kw0 = blockIdx.y * 32;

    __half* As[3];
    __half* Bs[3];
#pragma unroll
    for (int s = 0; s < 3; s++) {
        As[s] = stages + s * STAGE_HALVES;
        Bs[s] = As[s] + A_STAGE_HALVES;
    }

    float c[2][8][4];
#pragma unroll
    for (int i = 0; i < 2; i++)
#pragma unroll
        for (int j = 0; j < 8; j++)
#pragma unroll
            for (int q = 0; q < 4; q++) c[i][j][q] = 0.f;

    {
        uint32_t bb = (uint32_t)__cvta_generic_to_shared(bitsS);
#pragma unroll
        for (int i = 0; i < 2; i++) {
            int task = t + i * 512;
            int row = task >> 3, seg = task & 7;
            cp16(bb + (row * BITS_STRIDE + seg * 4) * 4,
                 g_adjbits + (size_t)(m0 + row) * 128 + kw0 + seg * 4);
        }
        CP_COMMIT();
    }

    auto load_B = [&](int slot, int kt) {
        const int k0 = kbase + kt * 64;
        uint32_t bbase = (uint32_t)__cvta_generic_to_shared(Bs[slot]);
#pragma unroll
        for (int i = 0; i < 4; i++) {
            int q = t + i * 512;
            int row = q >> 5, seg = q & 31;
            cp16(bbase + (row * B_STRIDE + seg * 8) * 2,
                 g_gh + (size_t)(k0 + row) * 256 + seg * 8);
        }
        CP_COMMIT();
    };

    const int xrow = t >> 2, xq = t & 3;
    auto expand_A = [&](int slot, int kt) {
        uint32_t w = bitsS[xrow * BITS_STRIDE + kt * 2 + (xq >> 1)];
        uint32_t b16 = (w >> ((xq & 1) * 16)) & 0xFFFFu;
        uint32_t u[8];
#pragma unroll
        for (int j = 0; j < 8; j++) {
            u[j] = ((b16 >> (2 * j)) & 1u) * 0x3C00u |
                   ((b16 >> (2 * j + 1)) & 1u) * 0x3C000000u;
        }
        __half* dst = As[slot] + xrow * A_STRIDE + xq * 16;
        *(uint4*)dst = make_uint4(u[0], u[1], u[2], u[3]);
        *(uint4*)(dst + 8) = make_uint4(u[4], u[5], u[6], u[7]);
    };

    load_B(0, 0);
    load_B(1, 1);
    load_B(2, 2);
    CP_WAIT3();
    __syncthreads();
    expand_A(0, 0);
    expand_A(1, 1);
    expand_A(2, 2);

    for (int kt = 0; kt < 16; ++kt) {
        const int slot = kt % 3;
        CP_WAIT2();
        __syncthreads();
        const __half* a_s = As[slot];
        const __half* b_s = Bs[slot];
#pragma unroll
        for (int ks = 0; ks < 4; ++ks) {
            uint32_t a[2][4];
#pragma unroll
            for (int mi = 0; mi < 2; ++mi) {
                int row = wm * 32 + mi * 16 + (lane & 15);
                int col = ks * 16 + ((lane >> 4) << 3);
                uint32_t addr =
                    (uint32_t)__cvta_generic_to_shared(a_s + row * A_STRIDE + col);
                ldsm4(a[mi][0], a[mi][1], a[mi][2], a[mi][3], addr);
            }
#pragma unroll
            for (int ng = 0; ng < 4; ++ng) {
                int krow = ks * 16 + (lane & 15);
                int col = wn * 64 + ng * 16 + ((lane >> 4) << 3);
                uint32_t b0, b1, b2, b3;
                uint32_t addr =
                    (uint32_t)__cvta_generic_to_shared(b_s + krow * B_STRIDE + col);
                ldsm4t(b0, b1, b2, b3, addr);
#pragma unroll
                for (int mi = 0; mi < 2; ++mi) {
                    mma_f16(c[mi][ng * 2][0], c[mi][ng * 2][1],
                            c[mi][ng * 2][2], c[mi][ng * 2][3],
                            a[mi][0], a[mi][1], a[mi][2], a[mi][3], b0, b1);
                    mma_f16(c[mi][ng * 2 + 1][0], c[mi][ng * 2 + 1][1],
                            c[mi][ng * 2 + 1][2], c[mi][ng * 2 + 1][3],
                            a[mi][0], a[mi][1], a[mi][2], a[mi][3], b2, b3);
                }
            }
        }
        __syncthreads();
        if (kt + 3 < 16) {
            expand_A(slot, kt + 3);
            load_B(slot, kt + 3);
        }
        CP_COMMIT();  // R3 pattern: unconditional extra group each iteration
    }

    // epilogue: fp32 partials
    float* dst = g_part + (size_t)blockIdx.y * NN * FF;
    const int g = lane >> 2, tg = lane & 3;
#pragma unroll
    for (int mi = 0; mi < 2; ++mi) {
        int row0 = m0 + wm * 32 + mi * 16 + g;
#pragma unroll
        for (int nb = 0; nb < 8; ++nb) {
            int col = wn * 64 + nb * 8 + tg * 2;
            float2 v0 = {c[mi][nb][0], c[mi][nb][1]};
            float2 v1 = {c[mi][nb][2], c[mi][nb][3]};
            *(float2*)(dst + (size_t)row0 * 256 + col) = v0;
            *(float2*)(dst + (size_t)(row0 + 8) * 256 + col) = v1;
        }
    }
}

// ---------------- kernel 7: out = relu(sum partials) * invS ----------------
__global__ __launch_bounds__(256) void relu_sum_kernel(float* __restrict__ out) {
    const float invS = g_invS;
    const size_t idx = (size_t)(blockIdx.x * 256 + threadIdx.x) * 4;
    float4 a = *(const float4*)(g_part + idx);
    float4 b = *(const float4*)(g_part + (size_t)NN * FF + idx);
    float4 c = *(const float4*)(g_part + 2 * (size_t)NN * FF + idx);
    float4 d = *(const float4*)(g_part + 3 * (size_t)NN * FF + idx);
    float4 v;
    v.x = fmaxf(a.x + b.x + c.x + d.x, 0.f) * invS;
    v.y = fmaxf(a.y + b.y + c.y + d.y, 0.f) * invS;
    v.z = fmaxf(a.z + b.z + c.z + d.z, 0.f) * invS;
    v.w = fmaxf(a.w + b.w + c.w + d.w, 0.f) * invS;
    *(float4*)(out + idx) = v;
}

// ---------------- launch ----------------
extern "C" void kernel_launch(void* const* d_in, const int* in_sizes, int n_in,
                              void* d_out, int out_size) {
    const float* x = (const float*)d_in[0];
    const int* adj = (const int*)d_in[1];
    const float* W = (const float*)d_in[2];
    const float* b = (const float*)d_in[3];
    const float* att_w = (const float*)d_in[4];
    // att_b cancels in the softmax ratio; unused.
    float* out = (float*)d_out;

    static bool attr_set = false;
    if (!attr_set) {
        cudaFuncSetAttribute(gemm_out_hmma_kernel,
                             cudaFuncAttributeMaxDynamicSharedMemorySize, SMEM_DYN);
        cudaFuncSetAttribute(gemm_h_hmma_kernel,
                             cudaFuncAttributeMaxDynamicSharedMemorySize, H_SMEM);
        attr_set = true;
    }

    convert_kernel<<<1088, 256>>>(x, W);
    gemm_h_hmma_kernel<<<dim3(64, 2), 256, H_SMEM>>>(b);
    a12_kernel<<<256, 256>>>(att_w);
    row_stats_kernel<<<512, 256>>>(adj);
    wnode_kernel<<<1, 1024>>>(adj);
    gscale_kernel<<<4096, 128>>>();
    gemm_out_hmma_kernel<<<dim3(32, 4), 512, SMEM_DYN>>>();
    relu_sum_kernel<<<1024, 256>>>(out);
}